// round 1
// baseline (speedup 1.0000x reference)
#include <cuda_runtime.h>
#include <math.h>

#define NN     200000
#define EE     8192
#define HH     64
#define TEDIM  32
#define EADIM  32
#define KF     192     // 2H + EA + TE
#define G4     256     // 4H
#define DFEAT  128
#define KZ     192     // H + D_FEAT
#define AA     50
#define SCAN_BLOCKS 148

// ---------------- device scratch (static, no runtime alloc) ----------------
__device__ float g_h[(size_t)NN * HH];     // node memory
__device__ float g_c[(size_t)NN * HH];     // LSTM cell state
__device__ int   g_done[NN];               // per-node completed-endpoint counter
__device__ int2  g_pairs[EE];              // (src, dst)
__device__ int   g_seq[2 * EE];            // per-endpoint rank among same-node endpoints
__device__ float g_Wf[KZ * AA];            // fused W_emb @ W_cls
__device__ float g_bf[AA];                 // fused bias

// ---------------- atomics / coherence helpers ----------------
__device__ __forceinline__ int ld_acq(const int* p) {
    int v;
    asm volatile("ld.global.acquire.gpu.b32 %0, [%1];" : "=r"(v) : "l"(p));
    return v;
}
__device__ __forceinline__ void st_rel(int* p, int v) {
    asm volatile("st.global.release.gpu.b32 [%0], %1;" :: "l"(p), "r"(v) : "memory");
}

// ---------------- kernel 1: init touched nodes + build pairs ----------------
__global__ void init_kernel(const int* __restrict__ eidx) {
    int idx = blockIdx.x * blockDim.x + threadIdx.x;   // [0, 2*EE*64)
    int n = idx >> 6;          // endpoint id
    int i = idx & 63;
    if (n >= 2 * EE) return;
    int e = n & (EE - 1);
    int s = n >> 13;
    int u = eidx[s * EE + e];
    g_h[(size_t)u * HH + i] = 0.f;
    g_c[(size_t)u * HH + i] = 0.f;
    if (i == 0) {
        g_done[u] = 0;
        if (s == 0) g_pairs[e] = make_int2(eidx[e], eidx[EE + e]);
    }
}

// ---------------- kernel 2: per-endpoint sequence numbers (brute, smem) ----
__global__ void __launch_bounds__(256) seq_kernel() {
    extern __shared__ int2 sp[];
    int t = threadIdx.x;
    for (int i = t; i < EE; i += 256) sp[i] = g_pairs[i];
    __syncthreads();
    int lane = t & 31, w = t >> 5;
    for (int n = blockIdx.x * 8 + w; n < 2 * EE; n += gridDim.x * 8) {
        int e = n >> 1, s = n & 1;
        int2 pe = sp[e];
        int u = s ? pe.y : pe.x;
        int cnt = 0;
        for (int j = lane; j < e; j += 32) {
            int2 p = sp[j];
            cnt += (p.x == u) + (p.y == u);
        }
        #pragma unroll
        for (int off = 16; off > 0; off >>= 1)
            cnt += __shfl_down_sync(0xffffffffu, cnt, off);
        if (lane == 0) g_seq[n] = cnt;
    }
}

// ---------------- kernel 3: fuse W_emb @ W_cls (linear-linear compose) -----
__global__ void fuse_kernel(const float* __restrict__ W_emb, const float* __restrict__ W_cls,
                            const float* __restrict__ b_emb, const float* __restrict__ b_cls) {
    int idx = blockIdx.x * blockDim.x + threadIdx.x;
    if (idx < KZ * AA) {
        int k = idx / AA, a = idx % AA;
        float s = 0.f;
        #pragma unroll 8
        for (int c = 0; c < HH; c++) s = fmaf(W_emb[k * HH + c], W_cls[c * AA + a], s);
        g_Wf[idx] = s;
    } else if (idx < KZ * AA + AA) {
        int a = idx - KZ * AA;
        float s = b_cls[a];
        for (int c = 0; c < HH; c++) s = fmaf(b_emb[c], W_cls[c * AA + a], s);
        g_bf[a] = s;
    }
}

// ---------------- kernel 4: persistent dataflow scan ----------------
__global__ void __launch_bounds__(512, 1) scan_kernel(
    const float* __restrict__ Wmsg, const float* __restrict__ bmsg,
    const float* __restrict__ Wih,  const float* __restrict__ Whh,
    const float* __restrict__ blstm, const float* __restrict__ tw,
    const float* __restrict__ tb,   const float* __restrict__ eattr,
    const float* __restrict__ etime)
{
    extern __shared__ float sm[];
    float* sWmsg  = sm;                          // 12288
    float* sWih   = sWmsg + KF * HH;             // 16384
    float* sWhh   = sWih + HH * G4;              // 16384
    float* sbmsg  = sWhh + HH * G4;              // 64
    float* sblstm = sbmsg + HH;                  // 256
    float* stw    = sblstm + G4;                 // 32
    float* stb    = stw + TEDIM;                 // 32
    float* sfeat  = stb + TEDIM;                 // 2*192
    float* scp    = sfeat + 2 * KF;              // 2*64
    float* smm    = scp + 2 * HH;                // 2*64
    float* sgate  = smm + 2 * HH;                // 2*256

    int t = threadIdx.x;
    for (int i = t; i < KF * HH; i += 512) sWmsg[i] = Wmsg[i];
    for (int i = t; i < HH * G4; i += 512) sWih[i] = Wih[i];
    for (int i = t; i < HH * G4; i += 512) sWhh[i] = Whh[i];
    if (t < HH)    sbmsg[t]  = bmsg[t];
    if (t < G4)    sblstm[t] = blstm[t];
    if (t < TEDIM) { stw[t] = tw[t]; stb[t] = tb[t]; }
    __syncthreads();

    for (int e = blockIdx.x; e < EE; e += gridDim.x) {
        int2 pr = g_pairs[e];
        int s0 = g_seq[2 * e], s1 = g_seq[2 * e + 1];

        if (t == 0) {  // dependency spin (bounded to avoid full-bench hang on a bug)
            int guard = 0;
            while (ld_acq(&g_done[pr.x]) != s0 && ++guard < (1 << 16)) {}
            guard = 0;
            while (ld_acq(&g_done[pr.y]) != s1 && ++guard < (1 << 16)) {}
        }
        __syncthreads();

        // load h,c (via L2 to bypass possibly-stale L1) + build feat rows
        // row0 = [hd, hs, ea, te]  (updates src) ; row1 = [hs, hd, ea, te] (updates dst)
        if (t < 64) {
            float v = __ldcg(&g_h[(size_t)pr.x * HH + t]);          // hs
            sfeat[KF + t] = v; sfeat[64 + t] = v;
        } else if (t < 128) {
            int i = t - 64;
            float v = __ldcg(&g_h[(size_t)pr.y * HH + i]);          // hd
            sfeat[i] = v; sfeat[KF + 64 + i] = v;
        } else if (t < 192) {
            int i = t - 128;
            scp[i] = __ldcg(&g_c[(size_t)pr.x * HH + i]);           // cs
        } else if (t < 256) {
            int i = t - 192;
            scp[64 + i] = __ldcg(&g_c[(size_t)pr.y * HH + i]);      // cd
        } else if (t < 288) {
            int i = t - 256;
            float v = eattr[e * EADIM + i];
            sfeat[128 + i] = v; sfeat[KF + 128 + i] = v;
        } else if (t < 320) {
            int i = t - 288;
            float tv = etime[e];
            float v = cosf(tv * stw[i] + stb[i]);
            sfeat[160 + i] = v; sfeat[KF + 160 + i] = v;
        }
        __syncthreads();

        // gemm1: m[2,64] = relu(feat[2,192] @ Wmsg[192,64] + b).  4 threads/output.
        {
            int o = t >> 2, p = t & 3;           // o in [0,128)
            int r = o >> 6, col = o & 63;
            const float4* f4 = (const float4*)(sfeat + r * KF + p * 48);
            float acc = 0.f;
            #pragma unroll
            for (int i2 = 0; i2 < 12; i2++) {
                float4 fv = f4[i2];
                int k = p * 48 + i2 * 4;
                acc = fmaf(fv.x, sWmsg[(k + 0) * HH + col], acc);
                acc = fmaf(fv.y, sWmsg[(k + 1) * HH + col], acc);
                acc = fmaf(fv.z, sWmsg[(k + 2) * HH + col], acc);
                acc = fmaf(fv.w, sWmsg[(k + 3) * HH + col], acc);
            }
            acc += __shfl_down_sync(0xffffffffu, acc, 2, 4);
            acc += __shfl_down_sync(0xffffffffu, acc, 1, 4);
            if (p == 0) smm[o] = fmaxf(acc + sbmsg[col], 0.f);
        }
        __syncthreads();

        // gemm2: gates[2,256] = m @ Wih + h @ Whh + b.  1 thread/output.
        {
            int r = t >> 8, j = t & 255;
            float acc = sblstm[j];
            const float4* m4 = (const float4*)(smm + r * HH);
            const float4* h4 = (const float4*)(sfeat + (1 - r) * KF); // hp[0]=hs, hp[1]=hd
            #pragma unroll
            for (int kb = 0; kb < 16; kb++) {
                float4 mv = m4[kb]; float4 hv = h4[kb];
                int k = kb * 4;
                acc = fmaf(mv.x, sWih[(k + 0) * G4 + j], acc);
                acc = fmaf(mv.y, sWih[(k + 1) * G4 + j], acc);
                acc = fmaf(mv.z, sWih[(k + 2) * G4 + j], acc);
                acc = fmaf(mv.w, sWih[(k + 3) * G4 + j], acc);
                acc = fmaf(hv.x, sWhh[(k + 0) * G4 + j], acc);
                acc = fmaf(hv.y, sWhh[(k + 1) * G4 + j], acc);
                acc = fmaf(hv.z, sWhh[(k + 2) * G4 + j], acc);
                acc = fmaf(hv.w, sWhh[(k + 3) * G4 + j], acc);
            }
            sgate[r * G4 + j] = acc;
        }
        __syncthreads();

        // LSTM elementwise + state write (dst slot wins on self-loop, like JAX)
        if (t < 128) {
            int r = t >> 6, c = t & 63;
            float gi = sgate[r * G4 + c];
            float gf = sgate[r * G4 + 64 + c];
            float gg = sgate[r * G4 + 128 + c];
            float go = sgate[r * G4 + 192 + c];
            float si = 1.f / (1.f + expf(-gi));
            float sf = 1.f / (1.f + expf(-gf));
            float so = 1.f / (1.f + expf(-go));
            float cn = sf * scp[r * HH + c] + si * tanhf(gg);
            float hn = so * tanhf(cn);
            int node = r ? pr.y : pr.x;
            if (!(pr.x == pr.y && r == 0)) {
                __stcg(&g_h[(size_t)node * HH + c], hn);
                __stcg(&g_c[(size_t)node * HH + c], cn);
            }
        }
        __syncthreads();

        if (t == 0) {
            __threadfence();
            if (pr.x == pr.y) {
                st_rel(&g_done[pr.x], s0 + 2);
            } else {
                st_rel(&g_done[pr.x], s0 + 1);
                st_rel(&g_done[pr.y], s1 + 1);
            }
        }
    }
}

// ---------------- kernel 5: epilogue  logits[e] = [h[dst]||x[dst]] @ Wf + bf
__global__ void __launch_bounds__(256) epilogue_kernel(const float* __restrict__ x,
                                                       const int* __restrict__ eidx,
                                                       float* __restrict__ out) {
    __shared__ float sWf[KZ * AA];
    __shared__ float sbf[AA];
    __shared__ float sCat[8][KZ];
    int t = threadIdx.x;
    for (int i = t; i < KZ * AA; i += 256) sWf[i] = g_Wf[i];
    if (t < AA) sbf[t] = g_bf[t];
    __syncthreads();
    int lane = t & 31, w = t >> 5;
    for (int e = blockIdx.x * 8 + w; e < EE; e += gridDim.x * 8) {
        int dst = eidx[EE + e];
        #pragma unroll
        for (int q = 0; q < 6; q++) {
            int k = lane + q * 32;
            sCat[w][k] = (k < HH) ? g_h[(size_t)dst * HH + k]
                                  : x[(size_t)dst * DFEAT + (k - HH)];
        }
        __syncwarp();
        float a0 = sbf[lane];
        float a1 = (lane < AA - 32) ? sbf[lane + 32] : 0.f;
        #pragma unroll 4
        for (int k = 0; k < KZ; k++) {
            float v = sCat[w][k];
            a0 = fmaf(v, sWf[k * AA + lane], a0);
            if (lane < AA - 32) a1 = fmaf(v, sWf[k * AA + lane + 32], a1);
        }
        out[(size_t)e * AA + lane] = a0;
        if (lane < AA - 32) out[(size_t)e * AA + lane + 32] = a1;
        __syncwarp();
    }
}

// ---------------- launch ----------------
extern "C" void kernel_launch(void* const* d_in, const int* in_sizes, int n_in,
                              void* d_out, int out_size) {
    const float* x      = (const float*)d_in[0];
    const int*   eidx   = (const int*)  d_in[1];
    const float* eattr  = (const float*)d_in[2];
    const float* etime  = (const float*)d_in[3];
    const float* time_w = (const float*)d_in[4];
    const float* time_b = (const float*)d_in[5];
    const float* W_msg  = (const float*)d_in[6];
    const float* b_msg  = (const float*)d_in[7];
    const float* W_ih   = (const float*)d_in[8];
    const float* W_hh   = (const float*)d_in[9];
    const float* b_lstm = (const float*)d_in[10];
    const float* W_emb  = (const float*)d_in[11];
    const float* b_emb  = (const float*)d_in[12];
    const float* W_cls  = (const float*)d_in[13];
    const float* b_cls  = (const float*)d_in[14];
    float* out = (float*)d_out;

    cudaFuncSetAttribute(seq_kernel, cudaFuncAttributeMaxDynamicSharedMemorySize,
                         EE * (int)sizeof(int2));
    cudaFuncSetAttribute(scan_kernel, cudaFuncAttributeMaxDynamicSharedMemorySize,
                         46592 * (int)sizeof(float));

    init_kernel<<<(2 * EE * 64) / 256, 256>>>(eidx);
    seq_kernel<<<128, 256, EE * sizeof(int2)>>>();
    fuse_kernel<<<(KZ * AA + AA + 255) / 256, 256>>>(W_emb, W_cls, b_emb, b_cls);
    scan_kernel<<<SCAN_BLOCKS, 512, 46592 * sizeof(float)>>>(
        W_msg, b_msg, W_ih, W_hh, b_lstm, time_w, time_b, eattr, etime);
    epilogue_kernel<<<256, 256>>>(x, eidx, out);
}

// round 3
// speedup vs baseline: 2.8825x; 2.8825x over previous
#include <cuda_runtime.h>
#include <math.h>

#define NN     200000
#define EE     8192
#define HH     64
#define TEDIM  32
#define EADIM  32
#define KF     192     // 2H + EA + TE
#define G4     256     // 4H
#define DFEAT  128
#define KZ     192     // H + D_FEAT
#define AA     50
#define SCAN_BLOCKS 148
#define NGROUP 8
#define NSTREAM (SCAN_BLOCKS * NGROUP)   // 1184 concurrent event streams

// ---------------- device scratch (static, no runtime alloc) ----------------
__device__ float g_h[(size_t)NN * HH];     // node memory
__device__ float g_c[(size_t)NN * HH];     // LSTM cell state
__device__ int   g_done[NN];               // per-node completed-endpoint counter
__device__ int2  g_pairs[EE];              // (src, dst)
__device__ int   g_seq[2 * EE];            // per-endpoint rank among same-node endpoints
__device__ float g_Wf[KZ * AA];            // fused W_emb @ W_cls
__device__ float g_bf[AA];                 // fused bias

// ---------------- atomics / coherence helpers ----------------
__device__ __forceinline__ int ld_acq(const int* p) {
    int v;
    asm volatile("ld.global.acquire.gpu.b32 %0, [%1];" : "=r"(v) : "l"(p));
    return v;
}
__device__ __forceinline__ void st_rel(int* p, int v) {
    asm volatile("st.global.release.gpu.b32 [%0], %1;" :: "l"(p), "r"(v) : "memory");
}
__device__ __forceinline__ void bar_group(int g) {
    asm volatile("bar.sync %0, 64;" :: "r"(g + 1) : "memory");
}
__device__ __forceinline__ float sigf(float x) {
    return 1.f / (1.f + __expf(-x));
}

// ---------------- kernel 1: init touched nodes + build pairs ----------------
__global__ void init_kernel(const int* __restrict__ eidx) {
    int idx = blockIdx.x * blockDim.x + threadIdx.x;   // [0, 2*EE*64)
    int n = idx >> 6;          // endpoint id
    int i = idx & 63;
    if (n >= 2 * EE) return;
    int e = n & (EE - 1);
    int s = n >> 13;
    int u = eidx[s * EE + e];
    g_h[(size_t)u * HH + i] = 0.f;
    g_c[(size_t)u * HH + i] = 0.f;
    if (i == 0) {
        g_done[u] = 0;
        if (s == 0) g_pairs[e] = make_int2(eidx[e], eidx[EE + e]);
    }
}

// ---------------- kernel 2: per-endpoint sequence numbers (brute, smem) ----
__global__ void __launch_bounds__(256) seq_kernel() {
    extern __shared__ int2 sp[];
    int t = threadIdx.x;
    for (int i = t; i < EE; i += 256) sp[i] = g_pairs[i];
    __syncthreads();
    int lane = t & 31, w = t >> 5;
    for (int n = blockIdx.x * 8 + w; n < 2 * EE; n += gridDim.x * 8) {
        int e = n >> 1, s = n & 1;
        int2 pe = sp[e];
        int u = s ? pe.y : pe.x;
        int cnt = 0;
        for (int j = lane; j < e; j += 32) {
            int2 p = sp[j];
            cnt += (p.x == u) + (p.y == u);
        }
        #pragma unroll
        for (int off = 16; off > 0; off >>= 1)
            cnt += __shfl_down_sync(0xffffffffu, cnt, off);
        if (lane == 0) g_seq[n] = cnt;
    }
}

// ---------------- kernel 3: fuse W_emb @ W_cls ----------------
__global__ void fuse_kernel(const float* __restrict__ W_emb, const float* __restrict__ W_cls,
                            const float* __restrict__ b_emb, const float* __restrict__ b_cls) {
    int idx = blockIdx.x * blockDim.x + threadIdx.x;
    if (idx < KZ * AA) {
        int k = idx / AA, a = idx % AA;
        float s = 0.f;
        #pragma unroll 8
        for (int c = 0; c < HH; c++) s = fmaf(W_emb[k * HH + c], W_cls[c * AA + a], s);
        g_Wf[idx] = s;
    } else if (idx < KZ * AA + AA) {
        int a = idx - KZ * AA;
        float s = b_cls[a];
        for (int c = 0; c < HH; c++) s = fmaf(b_emb[c], W_cls[c * AA + a], s);
        g_bf[a] = s;
    }
}

// ---------------- kernel 4: persistent dataflow scan, 8 groups/block ------
// smem float offsets
#define O_WMSG   0
#define O_WIH    12288
#define O_WHH    28672
#define O_BMSG   45056
#define O_BLSTM  45120
#define O_TW     45376
#define O_TB     45408
#define O_HP     45440          // float2[8][64]
#define O_COMM   46464          // float [8][64]
#define O_MP     46976          // float2[8][64]
#define SCAN_SMEM_F 48000

__global__ void __launch_bounds__(512, 1) scan_kernel(
    const float* __restrict__ Wmsg, const float* __restrict__ bmsg,
    const float* __restrict__ Wih,  const float* __restrict__ Whh,
    const float* __restrict__ blstm, const float* __restrict__ tw,
    const float* __restrict__ tb,   const float* __restrict__ eattr,
    const float* __restrict__ etime)
{
    extern __shared__ float sm[];
    float* sWmsg  = sm + O_WMSG;
    float* sWihP  = sm + O_WIH;
    float* sWhhP  = sm + O_WHH;
    float* sbmsg  = sm + O_BMSG;
    float* sblstm = sm + O_BLSTM;
    float* stw    = sm + O_TW;
    float* stb    = sm + O_TB;

    int t = threadIdx.x;
    int g = t >> 6, lt = t & 63;

    float2* sHp   = ((float2*)(sm + O_HP)) + g * 64;
    float*  sComm = sm + O_COMM + g * 64;
    float2* sMp   = ((float2*)(sm + O_MP)) + g * 64;

    // ---- load + permute weights (whole block) ----
    for (int i = t; i < KF * HH; i += 512) sWmsg[i] = Wmsg[i];
    for (int i = t; i < HH * G4; i += 512) {
        int k = i >> 8, j = i & 255;
        int p = ((k << 6) + (j & 63)) * 4 + (j >> 6);
        sWihP[p] = Wih[i];
        sWhhP[p] = Whh[i];
    }
    if (t < HH)    sbmsg[t]  = bmsg[t];
    if (t < G4)    sblstm[t] = blstm[t];
    if (t < TEDIM) { stw[t] = tw[t]; stb[t] = tb[t]; }
    __syncthreads();

    for (int e = blockIdx.x * NGROUP + g; e < EE; e += NSTREAM) {
        int2 pr = g_pairs[e];
        int s0 = g_seq[2 * e], s1 = g_seq[2 * e + 1];

        // every thread spins itself (acquire); no handoff barrier needed
        {
            int guard = 0;
            while ((ld_acq(&g_done[pr.x]) != s0 || ld_acq(&g_done[pr.y]) != s1)
                   && ++guard < (1 << 18)) {}
        }

        // ---- load state (L2-coherent) + build shared operands ----
        float hs = __ldcg(&g_h[(size_t)pr.x * HH + lt]);
        float hd = __ldcg(&g_h[(size_t)pr.y * HH + lt]);
        float cs = __ldcg(&g_c[(size_t)pr.x * HH + lt]);
        float cd = __ldcg(&g_c[(size_t)pr.y * HH + lt]);
        sHp[lt] = make_float2(hs, hd);
        if (lt < EADIM) {
            sComm[lt] = eattr[e * EADIM + lt];
        } else {
            int i = lt - EADIM;
            float tv = __ldg(&etime[e]);
            sComm[lt] = cosf(tv * stw[i] + stb[i]);
        }
        bar_group(g);

        // ---- gemm1: m[2,64] = relu(feat @ Wmsg + b). thread t -> col t ----
        // row0 = [hd, hs, ea, te] ; row1 = [hs, hd, ea, te]
        float a0 = sbmsg[lt], a1 = a0;
        #pragma unroll 8
        for (int k = 0; k < 64; k++) {
            float2 p = sHp[k];
            float w = sWmsg[k * HH + lt];
            a0 = fmaf(p.y, w, a0);
            a1 = fmaf(p.x, w, a1);
        }
        #pragma unroll 8
        for (int k = 0; k < 64; k++) {
            float2 p = sHp[k];
            float w = sWmsg[(64 + k) * HH + lt];
            a0 = fmaf(p.x, w, a0);
            a1 = fmaf(p.y, w, a1);
        }
        #pragma unroll 8
        for (int k = 0; k < 64; k++) {
            float f = sComm[k];
            float w = sWmsg[(128 + k) * HH + lt];
            a0 = fmaf(f, w, a0);
            a1 = fmaf(f, w, a1);
        }
        sMp[lt] = make_float2(fmaxf(a0, 0.f), fmaxf(a1, 0.f));
        bar_group(g);

        // ---- gemm2: gates = m@Wih + hp@Whh + b. thread t -> cell col t ----
        // acc[r][q]: r=row, q=gate (i,f,g,o). hp[0]=hs, hp[1]=hd.
        float ac00 = sblstm[lt],       ac01 = sblstm[lt + 64];
        float ac02 = sblstm[lt + 128], ac03 = sblstm[lt + 192];
        float ac10 = ac00, ac11 = ac01, ac12 = ac02, ac13 = ac03;
        #pragma unroll 8
        for (int k = 0; k < 64; k++) {
            float2 m = sMp[k];
            float2 h = sHp[k];
            float4 wi = *(const float4*)&sWihP[(k * 64 + lt) * 4];
            float4 wh = *(const float4*)&sWhhP[(k * 64 + lt) * 4];
            ac00 = fmaf(m.x, wi.x, ac00); ac01 = fmaf(m.x, wi.y, ac01);
            ac02 = fmaf(m.x, wi.z, ac02); ac03 = fmaf(m.x, wi.w, ac03);
            ac10 = fmaf(m.y, wi.x, ac10); ac11 = fmaf(m.y, wi.y, ac11);
            ac12 = fmaf(m.y, wi.z, ac12); ac13 = fmaf(m.y, wi.w, ac13);
            ac00 = fmaf(h.x, wh.x, ac00); ac01 = fmaf(h.x, wh.y, ac01);
            ac02 = fmaf(h.x, wh.z, ac02); ac03 = fmaf(h.x, wh.w, ac03);
            ac10 = fmaf(h.y, wh.x, ac10); ac11 = fmaf(h.y, wh.y, ac11);
            ac12 = fmaf(h.y, wh.z, ac12); ac13 = fmaf(h.y, wh.w, ac13);
        }

        // ---- LSTM elementwise in registers + state write ----
        bool selfloop = (pr.x == pr.y);
        {   // row 1 (dst) — always written
            float cn = sigf(ac11) * cd + sigf(ac10) * tanhf(ac12);
            float hn = sigf(ac13) * tanhf(cn);
            __stcg(&g_h[(size_t)pr.y * HH + lt], hn);
            __stcg(&g_c[(size_t)pr.y * HH + lt], cn);
        }
        if (!selfloop) {  // row 0 (src)
            float cn = sigf(ac01) * cs + sigf(ac00) * tanhf(ac02);
            float hn = sigf(ac03) * tanhf(cn);
            __stcg(&g_h[(size_t)pr.x * HH + lt], hn);
            __stcg(&g_c[(size_t)pr.x * HH + lt], cn);
        }
        bar_group(g);

        if (lt == 0) {
            __threadfence();
            if (selfloop) {
                st_rel(&g_done[pr.x], s0 + 2);
            } else {
                st_rel(&g_done[pr.x], s0 + 1);
                st_rel(&g_done[pr.y], s1 + 1);
            }
        }
    }
}

// ---------------- kernel 5: epilogue  logits[e] = [h[dst]||x[dst]] @ Wf + bf
__global__ void __launch_bounds__(256) epilogue_kernel(const float* __restrict__ x,
                                                       const int* __restrict__ eidx,
                                                       float* __restrict__ out) {
    __shared__ float sWf[KZ * AA];
    __shared__ float sbf[AA];
    __shared__ float sCat[8][KZ];
    int t = threadIdx.x;
    for (int i = t; i < KZ * AA; i += 256) sWf[i] = g_Wf[i];
    if (t < AA) sbf[t] = g_bf[t];
    __syncthreads();
    int lane = t & 31, w = t >> 5;
    for (int e = blockIdx.x * 8 + w; e < EE; e += gridDim.x * 8) {
        int dst = eidx[EE + e];
        #pragma unroll
        for (int q = 0; q < 6; q++) {
            int k = lane + q * 32;
            sCat[w][k] = (k < HH) ? g_h[(size_t)dst * HH + k]
                                  : x[(size_t)dst * DFEAT + (k - HH)];
        }
        __syncwarp();
        float a0 = sbf[lane];
        float a1 = (lane < AA - 32) ? sbf[lane + 32] : 0.f;
        #pragma unroll 4
        for (int k = 0; k < KZ; k++) {
            float v = sCat[w][k];
            a0 = fmaf(v, sWf[k * AA + lane], a0);
            if (lane < AA - 32) a1 = fmaf(v, sWf[k * AA + lane + 32], a1);
        }
        out[(size_t)e * AA + lane] = a0;
        if (lane < AA - 32) out[(size_t)e * AA + lane + 32] = a1;
        __syncwarp();
    }
}

// ---------------- launch ----------------
extern "C" void kernel_launch(void* const* d_in, const int* in_sizes, int n_in,
                              void* d_out, int out_size) {
    const float* x      = (const float*)d_in[0];
    const int*   eidx   = (const int*)  d_in[1];
    const float* eattr  = (const float*)d_in[2];
    const float* etime  = (const float*)d_in[3];
    const float* time_w = (const float*)d_in[4];
    const float* time_b = (const float*)d_in[5];
    const float* W_msg  = (const float*)d_in[6];
    const float* b_msg  = (const float*)d_in[7];
    const float* W_ih   = (const float*)d_in[8];
    const float* W_hh   = (const float*)d_in[9];
    const float* b_lstm = (const float*)d_in[10];
    const float* W_emb  = (const float*)d_in[11];
    const float* b_emb  = (const float*)d_in[12];
    const float* W_cls  = (const float*)d_in[13];
    const float* b_cls  = (const float*)d_in[14];
    float* out = (float*)d_out;

    cudaFuncSetAttribute(seq_kernel, cudaFuncAttributeMaxDynamicSharedMemorySize,
                         EE * (int)sizeof(int2));
    cudaFuncSetAttribute(scan_kernel, cudaFuncAttributeMaxDynamicSharedMemorySize,
                         SCAN_SMEM_F * (int)sizeof(float));

    init_kernel<<<(2 * EE * 64) / 256, 256>>>(eidx);
    seq_kernel<<<128, 256, EE * sizeof(int2)>>>();
    fuse_kernel<<<(KZ * AA + AA + 255) / 256, 256>>>(W_emb, W_cls, b_emb, b_cls);
    scan_kernel<<<SCAN_BLOCKS, 512, SCAN_SMEM_F * sizeof(float)>>>(
        W_msg, b_msg, W_ih, W_hh, b_lstm, time_w, time_b, eattr, etime);
    epilogue_kernel<<<256, 256>>>(x, eidx, out);
}